// round 1
// baseline (speedup 1.0000x reference)
#include <cuda_runtime.h>

// Problem constants
#define BATCH    8192
#define IN_DIM   512
#define NUM_TREE 64
#define NI       31          // internal nodes per tree
#define NL       32          // leaves per tree
#define ODIM     16

// Tiling
#define MT       32          // rows per CTA
#define TG       8           // trees per group
#define GN       (TG * NI)   // 248 nodes per group
#define KC       32          // k-chunk staged in smem
#define THREADS  256
#define XS_STRIDE 513        // 512 + 1 pad -> conflict-free strided row reads
#define WS_STRIDE 256        // 248 nodes padded to 256

// Softmaxed leaf table, computed each launch by a tiny kernel (deterministic).
__device__ __align__(16) float g_leafs_sm[NUM_TREE * NL * ODIM];

__global__ void leafs_softmax_kernel(const float* __restrict__ leafs) {
    int i = blockIdx.x * blockDim.x + threadIdx.x;   // one (tree, leaf) per thread
    if (i >= NUM_TREE * NL) return;
    const float* src = leafs + i * ODIM;
    float m = src[0];
#pragma unroll
    for (int o = 1; o < ODIM; o++) m = fmaxf(m, src[o]);
    float e[ODIM];
    float s = 0.f;
#pragma unroll
    for (int o = 0; o < ODIM; o++) { e[o] = __expf(src[o] - m); s += e[o]; }
    float inv = 1.0f / s;
#pragma unroll
    for (int o = 0; o < ODIM; o++) g_leafs_sm[i * ODIM + o] = e[o] * inv;
}

__global__ __launch_bounds__(THREADS, 2)
void dndf_fused_kernel(const float* __restrict__ x,
                       const float* __restrict__ W,
                       const float* __restrict__ b,
                       float* __restrict__ out) {
    extern __shared__ float smem[];
    float* x_s = smem;                       // [MT][XS_STRIDE]  (65,664 B)
    float* w_s = smem + MT * XS_STRIDE;      // [KC][WS_STRIDE]  (32,768 B), reused as p_s [MT][WS_STRIDE]

    const int tid = threadIdx.x;
    const int row_base = blockIdx.x * MT;

    // ---- stage x tile [MT x IN_DIM] into smem (stride-513 padded) ----
    const float4* x4 = reinterpret_cast<const float4*>(x);
    for (int idx = tid; idx < MT * (IN_DIM / 4); idx += THREADS) {
        int r  = idx >> 7;        // / 128
        int kq = idx & 127;
        float4 v = x4[(row_base + r) * (IN_DIM / 4) + kq];
        float* d = &x_s[r * XS_STRIDE + kq * 4];
        d[0] = v.x; d[1] = v.y; d[2] = v.z; d[3] = v.w;
    }

    // GEMM-phase mapping: thread tile = 4 rows x 8 nodes
    const int rg = tid & 7;            // row group: rows 4*rg .. 4*rg+3
    const int ng = tid >> 3;           // node group: nodes 8*ng .. 8*ng+7 (ng==31 idle)
    const bool gemm_active = (ng < 31);

    // Routing-phase mapping: one (row, tree) per thread
    const int row2 = tid >> 3;         // 0..31
    const int tt   = tid & 7;          // tree within group

    float out_acc[ODIM];
#pragma unroll
    for (int o = 0; o < ODIM; o++) out_acc[o] = 0.f;

    const float4* W4 = reinterpret_cast<const float4*>(W);

    for (int g = 0; g < NUM_TREE / TG; g++) {
        const int node_base = g * GN;          // global W row of this group's first node

        float acc[4][8];
#pragma unroll
        for (int i = 0; i < 4; i++)
#pragma unroll
            for (int j = 0; j < 8; j++) acc[i][j] = 0.f;

        // ---- GEMM: net[32][248] += x_tile @ W_group^T over K=512 in KC chunks ----
        for (int kc = 0; kc < IN_DIM; kc += KC) {
            __syncthreads();   // previous consumers of w_s done (covers x_s on first pass too)
            // load W chunk transposed: w_s[kk][n]
            for (int idx = tid; idx < GN * (KC / 4); idx += THREADS) {
                int n  = idx >> 3;     // / (KC/4)
                int kq = idx & 7;
                float4 v = W4[(node_base + n) * (IN_DIM / 4) + (kc >> 2) + kq];
                w_s[(kq * 4 + 0) * WS_STRIDE + n] = v.x;
                w_s[(kq * 4 + 1) * WS_STRIDE + n] = v.y;
                w_s[(kq * 4 + 2) * WS_STRIDE + n] = v.z;
                w_s[(kq * 4 + 3) * WS_STRIDE + n] = v.w;
            }
            __syncthreads();

            if (gemm_active) {
                const float* xp = &x_s[(rg * 4) * XS_STRIDE + kc];
                const float* wp = &w_s[ng * 8];
#pragma unroll 8
                for (int kk = 0; kk < KC; kk++) {
                    float xv[4];
#pragma unroll
                    for (int i = 0; i < 4; i++) xv[i] = xp[i * XS_STRIDE + kk];
                    float4 w0 = *reinterpret_cast<const float4*>(&wp[kk * WS_STRIDE]);
                    float4 w1 = *reinterpret_cast<const float4*>(&wp[kk * WS_STRIDE + 4]);
                    float wv[8] = {w0.x, w0.y, w0.z, w0.w, w1.x, w1.y, w1.z, w1.w};
#pragma unroll
                    for (int i = 0; i < 4; i++)
#pragma unroll
                        for (int j = 0; j < 8; j++)
                            acc[i][j] = fmaf(xv[i], wv[j], acc[i][j]);
                }
            }
        }
        __syncthreads();   // all GEMM reads of w_s complete -> safe to overwrite with p

        // ---- sigmoid(net + b) into p_s (= w_s) ----
        if (gemm_active) {
#pragma unroll
            for (int j = 0; j < 8; j++) {
                float bj = b[node_base + ng * 8 + j];
#pragma unroll
                for (int i = 0; i < 4; i++) {
                    float v = acc[i][j] + bj;
                    float p = 1.0f / (1.0f + __expf(-v));
                    w_s[(rg * 4 + i) * WS_STRIDE + ng * 8 + j] = p;
                }
            }
        }
        __syncthreads();

        // ---- routing + leaf contraction: thread = (row2, tree tt) ----
        {
            const float* P = &w_s[row2 * WS_STRIDE + tt * NI];
            float p0 = P[0];
            float a0 = p0, a1 = 1.0f - p0;
            float bb[4], cc[8], dd[16], rr[32];
            {
                float p1 = P[1], p2 = P[2];
                bb[0] = a0 * p1; bb[1] = a0 * (1.0f - p1);
                bb[2] = a1 * p2; bb[3] = a1 * (1.0f - p2);
            }
#pragma unroll
            for (int j = 0; j < 4; j++) {
                float pv = P[3 + j];
                cc[2 * j]     = bb[j] * pv;
                cc[2 * j + 1] = bb[j] * (1.0f - pv);
            }
#pragma unroll
            for (int j = 0; j < 8; j++) {
                float pv = P[7 + j];
                dd[2 * j]     = cc[j] * pv;
                dd[2 * j + 1] = cc[j] * (1.0f - pv);
            }
#pragma unroll
            for (int j = 0; j < 16; j++) {
                float pv = P[15 + j];
                rr[2 * j]     = dd[j] * pv;
                rr[2 * j + 1] = dd[j] * (1.0f - pv);
            }

            const float4* ls4 = reinterpret_cast<const float4*>(
                &g_leafs_sm[((g * TG + tt) * NL) * ODIM]);
#pragma unroll
            for (int l = 0; l < NL; l++) {
                float rl = rr[l];
                float4 v0 = ls4[l * 4 + 0];
                float4 v1 = ls4[l * 4 + 1];
                float4 v2 = ls4[l * 4 + 2];
                float4 v3 = ls4[l * 4 + 3];
                out_acc[0]  = fmaf(rl, v0.x, out_acc[0]);
                out_acc[1]  = fmaf(rl, v0.y, out_acc[1]);
                out_acc[2]  = fmaf(rl, v0.z, out_acc[2]);
                out_acc[3]  = fmaf(rl, v0.w, out_acc[3]);
                out_acc[4]  = fmaf(rl, v1.x, out_acc[4]);
                out_acc[5]  = fmaf(rl, v1.y, out_acc[5]);
                out_acc[6]  = fmaf(rl, v1.z, out_acc[6]);
                out_acc[7]  = fmaf(rl, v1.w, out_acc[7]);
                out_acc[8]  = fmaf(rl, v2.x, out_acc[8]);
                out_acc[9]  = fmaf(rl, v2.y, out_acc[9]);
                out_acc[10] = fmaf(rl, v2.z, out_acc[10]);
                out_acc[11] = fmaf(rl, v2.w, out_acc[11]);
                out_acc[12] = fmaf(rl, v3.x, out_acc[12]);
                out_acc[13] = fmaf(rl, v3.y, out_acc[13]);
                out_acc[14] = fmaf(rl, v3.z, out_acc[14]);
                out_acc[15] = fmaf(rl, v3.w, out_acc[15]);
            }
        }
        __syncthreads();   // routing reads of p_s done before next group's W load
    }

    // ---- reduce over the 8 tree-lanes sharing a row (lanes row*8+t are contiguous) ----
#pragma unroll
    for (int o = 0; o < ODIM; o++) {
        out_acc[o] += __shfl_xor_sync(0xffffffffu, out_acc[o], 1);
        out_acc[o] += __shfl_xor_sync(0xffffffffu, out_acc[o], 2);
        out_acc[o] += __shfl_xor_sync(0xffffffffu, out_acc[o], 4);
    }
    if (tt == 0) {
        float4* dst = reinterpret_cast<float4*>(out + (size_t)(row_base + row2) * ODIM);
        const float s = 1.0f / NUM_TREE;
        dst[0] = make_float4(out_acc[0] * s,  out_acc[1] * s,  out_acc[2] * s,  out_acc[3] * s);
        dst[1] = make_float4(out_acc[4] * s,  out_acc[5] * s,  out_acc[6] * s,  out_acc[7] * s);
        dst[2] = make_float4(out_acc[8] * s,  out_acc[9] * s,  out_acc[10] * s, out_acc[11] * s);
        dst[3] = make_float4(out_acc[12] * s, out_acc[13] * s, out_acc[14] * s, out_acc[15] * s);
    }
}

extern "C" void kernel_launch(void* const* d_in, const int* in_sizes, int n_in,
                              void* d_out, int out_size) {
    const float* x     = (const float*)d_in[0];   // [8192, 512]
    const float* W     = (const float*)d_in[1];   // [1984, 512]
    const float* b     = (const float*)d_in[2];   // [1984]
    const float* leafs = (const float*)d_in[3];   // [64, 32, 16]
    float* out = (float*)d_out;                   // [8192, 16]

    leafs_softmax_kernel<<<(NUM_TREE * NL + 255) / 256, 256>>>(leafs);

    const int smem_bytes = (MT * XS_STRIDE + KC * WS_STRIDE) * (int)sizeof(float); // 98,432 B
    static bool attr_set = false;
    // cudaFuncSetAttribute is an immediate host-side API (not a stream op);
    // calling it unconditionally is also graph-capture safe.
    cudaFuncSetAttribute(dndf_fused_kernel,
                         cudaFuncAttributeMaxDynamicSharedMemorySize, smem_bytes);
    (void)attr_set;

    dndf_fused_kernel<<<BATCH / MT, THREADS, smem_bytes>>>(x, W, b, out);
}

// round 4
// speedup vs baseline: 2.8113x; 2.8113x over previous
#include <cuda_runtime.h>
#include <cuda_bf16.h>
#include <cstdint>

// ---------------- problem constants ----------------
#define BATCH    8192
#define IN_DIM   512
#define NUM_TREE 64
#define NI       31
#define NL       32
#define ODIM     16

// ---------------- GEMM tiling ----------------
#define KP       1536        // packed K: [xh | xh | xl] vs [wh | wl | wh]
#define BM       128
#define BN       128         // 4 trees * 32 padded cols
#define BK       32
#define NKCH     (KP / BK)   // 48
#define NSTAGE   4
#define THREADS  256
#define APITCH   40          // bf16 elems per smem row (32 + 8 pad -> 80B stride)
#define NGRP     16          // N groups (16 * 128 = 2048 padded nodes)

#define STAGE_BYTES   20480u                 // A(10240) + B(10240)
#define SMEM_TOTAL    (STAGE_BYTES * NSTAGE) // 81920
// union region (reused after mainloop):
#define P_PITCH   133
#define UOFF_P    0u                         // float[128*133] = 68096 B
#define UOFF_LF   68096u                     // float[4*32*16] = 8192 B
#define UOFF_BIAS 76288u                     // float[128]     = 512 B

// ---------------- device scratch ----------------
__device__ __align__(16) __nv_bfloat16 g_A[(size_t)BATCH * KP];     // 25.2 MB
__device__ __align__(16) __nv_bfloat16 g_B[(size_t)2048 * KP];      // 6.3 MB
__device__ __align__(16) float g_bp[2048];
__device__ __align__(16) float g_leafs_sm[NUM_TREE * NL * ODIM];
__device__ __align__(16) float g_outp[(size_t)NGRP * BATCH * ODIM]; // 8 MB

// ---------------- helpers ----------------
__device__ __forceinline__ uint32_t smem_u32(const void* p) {
    uint32_t a;
    asm("{ .reg .u64 t; cvta.to.shared.u64 t, %1; cvt.u32.u64 %0, t; }" : "=r"(a) : "l"(p));
    return a;
}
__device__ __forceinline__ void cp16(uint32_t dst, const void* src) {
    asm volatile("cp.async.cg.shared.global [%0], [%1], 16;" :: "r"(dst), "l"(src));
}
__device__ __forceinline__ void ldm_x4(uint32_t& r0, uint32_t& r1, uint32_t& r2, uint32_t& r3,
                                       uint32_t addr) {
    asm volatile("ldmatrix.sync.aligned.m8n8.x4.shared.b16 {%0,%1,%2,%3}, [%4];"
                 : "=r"(r0), "=r"(r1), "=r"(r2), "=r"(r3) : "r"(addr));
}
__device__ __forceinline__ void mma_bf16(float& c0, float& c1, float& c2, float& c3,
                                         uint32_t a0, uint32_t a1, uint32_t a2, uint32_t a3,
                                         uint32_t b0, uint32_t b1) {
    asm volatile("mma.sync.aligned.m16n8k16.row.col.f32.bf16.bf16.f32 "
                 "{%0,%1,%2,%3}, {%4,%5,%6,%7}, {%8,%9}, {%0,%1,%2,%3};"
                 : "+f"(c0), "+f"(c1), "+f"(c2), "+f"(c3)
                 : "r"(a0), "r"(a1), "r"(a2), "r"(a3), "r"(b0), "r"(b1));
}

// ---------------- prep kernels ----------------
__global__ void leafs_softmax_kernel(const float* __restrict__ leafs) {
    int i = blockIdx.x * blockDim.x + threadIdx.x;
    if (i >= NUM_TREE * NL) return;
    const float* src = leafs + i * ODIM;
    float m = src[0];
#pragma unroll
    for (int o = 1; o < ODIM; o++) m = fmaxf(m, src[o]);
    float e[ODIM], sum = 0.f;
#pragma unroll
    for (int o = 0; o < ODIM; o++) { e[o] = __expf(src[o] - m); sum += e[o]; }
    float inv = 1.0f / sum;
#pragma unroll
    for (int o = 0; o < ODIM; o++) g_leafs_sm[i * ODIM + o] = e[o] * inv;
}

__global__ void prep_x_kernel(const float* __restrict__ x) {
    int i = blockIdx.x * blockDim.x + threadIdx.x;   // 8192*256 float2s
    int m = i >> 8;
    int k2 = i & 255;
    float2 v = ((const float2*)x)[i];
    __nv_bfloat16 h0 = __float2bfloat16(v.x);
    __nv_bfloat16 h1 = __float2bfloat16(v.y);
    __nv_bfloat162 hh; hh.x = h0; hh.y = h1;
    __nv_bfloat162 ll;
    ll.x = __float2bfloat16(v.x - __bfloat162float(h0));
    ll.y = __float2bfloat16(v.y - __bfloat162float(h1));
    size_t base = (size_t)m * KP + 2 * k2;
    *(__nv_bfloat162*)&g_A[base]        = hh;   // slab 0: xh
    *(__nv_bfloat162*)&g_A[base + 512]  = hh;   // slab 1: xh
    *(__nv_bfloat162*)&g_A[base + 1024] = ll;   // slab 2: xl
}

// B rows padded: row r -> tree r>>5, node r&31 (node 31 = zero); slabs [wh | wl | wh]
__global__ void prep_w_kernel(const float* __restrict__ W, const float* __restrict__ b) {
    int row = blockIdx.y;                               // 0..2047
    int k2  = blockIdx.x * blockDim.x + threadIdx.x;    // 0..767
    int t = row >> 5, ii = row & 31;
    int outcol = 2 * k2;
    int slab = outcol >> 9;
    int kk = outcol & 511;
    __nv_bfloat162 val;
    if (ii < 31) {
        const float2 wv = *(const float2*)&W[((size_t)(t * 31 + ii)) * IN_DIM + kk];
        __nv_bfloat16 h0 = __float2bfloat16(wv.x);
        __nv_bfloat16 h1 = __float2bfloat16(wv.y);
        if (slab == 1) {
            val.x = __float2bfloat16(wv.x - __bfloat162float(h0));
            val.y = __float2bfloat16(wv.y - __bfloat162float(h1));
        } else { val.x = h0; val.y = h1; }
    } else {
        val.x = __float2bfloat16(0.f); val.y = __float2bfloat16(0.f);
    }
    *(__nv_bfloat162*)&g_B[(size_t)row * KP + outcol] = val;
    if (k2 == 0) g_bp[row] = (ii < 31) ? b[t * 31 + ii] : 0.f;
}

// ---------------- fused GEMM (mma.sync) + routing kernel ----------------
__global__ __launch_bounds__(THREADS)
void dndf_mma_kernel() {
    extern __shared__ char smem[];
    const uint32_t sb = smem_u32(smem);

    const int tid = threadIdx.x;
    const int wid = tid >> 5;
    const int lid = tid & 31;
    const int wm = wid & 1;          // 2 m-groups of 64
    const int wn = wid >> 1;         // 4 n-groups of 32
    const int mrow_base = blockIdx.y * BM;
    const int ncol_base = blockIdx.x * BN;

    // cp.async mapping (per thread: 2 A segs + 2 B segs per stage)
    const int r_a  = tid >> 2;        // 0..63 (+64 on second it)
    const int sg_a = tid & 3;

    // ldmatrix lane offsets (bytes within stage A/B regions)
    const int a_row = (lid & 7) + ((lid >> 3) & 1) * 8;
    const int a_k8  = (lid >> 4) * 8;
    const int b_row = (lid & 7) + ((lid >> 4) & 1) * 8;
    const int b_k8  = ((lid >> 3) & 1) * 8;
    uint32_t aoff[4], boff[2];
#pragma unroll
    for (int mi = 0; mi < 4; mi++)
        aoff[mi] = ((wm * 64 + mi * 16 + a_row) * APITCH + a_k8) * 2;
#pragma unroll
    for (int nb = 0; nb < 2; nb++)
        boff[nb] = 10240u + ((wn * 32 + nb * 16 + b_row) * APITCH + b_k8) * 2;

    float acc[4][4][4];
#pragma unroll
    for (int i = 0; i < 4; i++)
#pragma unroll
        for (int j = 0; j < 4; j++)
#pragma unroll
            for (int r = 0; r < 4; r++) acc[i][j][r] = 0.f;

    // ---- prefetch stages 0..NSTAGE-2 ----
#pragma unroll
    for (int s = 0; s < NSTAGE - 1; s++) {
        const uint32_t st = sb + s * STAGE_BYTES;
        const int kbase = s * BK;
#pragma unroll
        for (int it = 0; it < 2; it++) {
            int r = r_a + it * 64;
            cp16(st + (uint32_t)(r * APITCH + sg_a * 8) * 2,
                 (const char*)g_A + ((size_t)(mrow_base + r) * KP + kbase + sg_a * 8) * 2);
        }
#pragma unroll
        for (int it = 0; it < 2; it++) {
            int r = r_a + it * 64;
            cp16(st + 10240u + (uint32_t)(r * APITCH + sg_a * 8) * 2,
                 (const char*)g_B + ((size_t)(ncol_base + r) * KP + kbase + sg_a * 8) * 2);
        }
        asm volatile("cp.async.commit_group;" ::: "memory");
    }

    // ---- mainloop ----
#pragma unroll 1
    for (int c = 0; c < NKCH; c++) {
        asm volatile("cp.async.wait_group %0;" :: "n"(NSTAGE - 2) : "memory");
        __syncthreads();

        const int cn = c + NSTAGE - 1;
        if (cn < NKCH) {
            const uint32_t st = sb + (cn & 3) * STAGE_BYTES;
            const int kbase = cn * BK;
#pragma unroll
            for (int it = 0; it < 2; it++) {
                int r = r_a + it * 64;
                cp16(st + (uint32_t)(r * APITCH + sg_a * 8) * 2,
                     (const char*)g_A + ((size_t)(mrow_base + r) * KP + kbase + sg_a * 8) * 2);
            }
#pragma unroll
            for (int it = 0; it < 2; it++) {
                int r = r_a + it * 64;
                cp16(st + 10240u + (uint32_t)(r * APITCH + sg_a * 8) * 2,
                     (const char*)g_B + ((size_t)(ncol_base + r) * KP + kbase + sg_a * 8) * 2);
            }
        }
        asm volatile("cp.async.commit_group;" ::: "memory");

        const uint32_t st = sb + (c & 3) * STAGE_BYTES;
#pragma unroll
        for (int kk = 0; kk < 2; kk++) {   // two k16 steps per BK=32
            uint32_t a[4][4], b[2][4];
#pragma unroll
            for (int mi = 0; mi < 4; mi++)
                ldm_x4(a[mi][0], a[mi][1], a[mi][2], a[mi][3], st + aoff[mi] + kk * 32);
#pragma unroll
            for (int nb = 0; nb < 2; nb++)
                ldm_x4(b[nb][0], b[nb][1], b[nb][2], b[nb][3], st + boff[nb] + kk * 32);
#pragma unroll
            for (int mi = 0; mi < 4; mi++) {
#pragma unroll
                for (int nb = 0; nb < 2; nb++) {
                    mma_bf16(acc[mi][nb * 2][0],     acc[mi][nb * 2][1],
                             acc[mi][nb * 2][2],     acc[mi][nb * 2][3],
                             a[mi][0], a[mi][1], a[mi][2], a[mi][3],
                             b[nb][0], b[nb][1]);
                    mma_bf16(acc[mi][nb * 2 + 1][0], acc[mi][nb * 2 + 1][1],
                             acc[mi][nb * 2 + 1][2], acc[mi][nb * 2 + 1][3],
                             a[mi][0], a[mi][1], a[mi][2], a[mi][3],
                             b[nb][2], b[nb][3]);
                }
            }
        }
    }

    asm volatile("cp.async.wait_group 0;" ::: "memory");
    __syncthreads();   // mainloop done; smem free for reuse

    // ---- stage bias + leaf tables ----
    float* p_s    = (float*)(smem + UOFF_P);
    float* lf_s   = (float*)(smem + UOFF_LF);
    float* bias_s = (float*)(smem + UOFF_BIAS);
    if (tid < 128) bias_s[tid] = g_bp[ncol_base + tid];
    {
        const float4* src = (const float4*)&g_leafs_sm[(size_t)(blockIdx.x * 4) * NL * ODIM];
        float4* dst = (float4*)lf_s;
#pragma unroll
        for (int i = tid; i < 4 * NL * ODIM / 4; i += THREADS) dst[i] = src[i];
    }
    __syncthreads();

    // ---- sigmoid(acc + bias) -> p_s, tree-interleaved: p_s[row][node*4 + tree] ----
    const int lr = lid >> 2;          // lane row 0..7
    const int lc = (lid & 3) * 2;     // lane col 0,2,4,6
#pragma unroll
    for (int mi = 0; mi < 4; mi++) {
#pragma unroll
        for (int ni = 0; ni < 4; ni++) {
            const int colb = wn * 32 + ni * 8 + lc;
            const int rowb = wm * 64 + mi * 16 + lr;
#pragma unroll
            for (int r = 0; r < 4; r++) {
                const int row = rowb + (r >> 1) * 8;
                const int col = colb + (r & 1);           // 0..127 = tree*32 + node
                const int icol = (col & 31) * 4 + (col >> 5);
                const float v = acc[mi][ni][r] + bias_s[col];
                p_s[row * P_PITCH + icol] = 1.0f / (1.0f + __expf(-v));
            }
        }
    }
    __syncthreads();

    // ---- routing + leaf contraction ----
    // warp wid owns rows [wid*16, wid*16+16); lane l = (row_quad = l>>2, tree = l&3).
    // 4 trees of a row live in one lane-quad -> shfl_xor(1,2) sums them. No p_s writes.
    {
        const int t = lid & 3;
        const float* lfb = &lf_s[(t * NL) * ODIM];
#pragma unroll
        for (int j = 0; j < 2; j++) {
            const int row = wid * 16 + (lid >> 2) + j * 8;
            const float* P = &p_s[row * P_PITCH];

            float p[NI];
#pragma unroll
            for (int i = 0; i < NI; i++) p[i] = P[i * 4 + t];

            float bb[4], cc[8], dd[16], rr[32];
            {
                float a0 = p[0], a1 = 1.0f - p[0];
                bb[0] = a0 * p[1]; bb[1] = a0 * (1.0f - p[1]);
                bb[2] = a1 * p[2]; bb[3] = a1 * (1.0f - p[2]);
            }
#pragma unroll
            for (int q = 0; q < 4; q++) {
                float pv = p[3 + q];
                cc[2 * q] = bb[q] * pv; cc[2 * q + 1] = bb[q] * (1.0f - pv);
            }
#pragma unroll
            for (int q = 0; q < 8; q++) {
                float pv = p[7 + q];
                dd[2 * q] = cc[q] * pv; dd[2 * q + 1] = cc[q] * (1.0f - pv);
            }
#pragma unroll
            for (int q = 0; q < 16; q++) {
                float pv = p[15 + q];
                rr[2 * q] = dd[q] * pv; rr[2 * q + 1] = dd[q] * (1.0f - pv);
            }

            float oacc[ODIM];
#pragma unroll
            for (int o = 0; o < ODIM; o++) oacc[o] = 0.f;
            const float4* ls4 = (const float4*)lfb;
#pragma unroll
            for (int l = 0; l < NL; l++) {
                float rl = rr[l];
                float4 v0 = ls4[l * 4 + 0], v1 = ls4[l * 4 + 1];
                float4 v2 = ls4[l * 4 + 2], v3 = ls4[l * 4 + 3];
                oacc[0]  = fmaf(rl, v0.x, oacc[0]);  oacc[1]  = fmaf(rl, v0.y, oacc[1]);
                oacc[2]  = fmaf(rl, v0.z, oacc[2]);  oacc[3]  = fmaf(rl, v0.w, oacc[3]);
                oacc[4]  = fmaf(rl, v1.x, oacc[4]);  oacc[5]  = fmaf(rl, v1.y, oacc[5]);
                oacc[6]  = fmaf(rl, v1.z, oacc[6]);  oacc[7]  = fmaf(rl, v1.w, oacc[7]);
                oacc[8]  = fmaf(rl, v2.x, oacc[8]);  oacc[9]  = fmaf(rl, v2.y, oacc[9]);
                oacc[10] = fmaf(rl, v2.z, oacc[10]); oacc[11] = fmaf(rl, v2.w, oacc[11]);
                oacc[12] = fmaf(rl, v3.x, oacc[12]); oacc[13] = fmaf(rl, v3.y, oacc[13]);
                oacc[14] = fmaf(rl, v3.z, oacc[14]); oacc[15] = fmaf(rl, v3.w, oacc[15]);
            }

            // sum the 4 trees of this row (lane-quad butterfly)
#pragma unroll
            for (int o = 0; o < ODIM; o++) {
                oacc[o] += __shfl_xor_sync(0xffffffffu, oacc[o], 1);
                oacc[o] += __shfl_xor_sync(0xffffffffu, oacc[o], 2);
            }
            // all 4 lanes now hold the row sum; lane t writes float4 quarter t
            float4 v = make_float4(oacc[t * 4 + 0], oacc[t * 4 + 1],
                                   oacc[t * 4 + 2], oacc[t * 4 + 3]);
            *(float4*)&g_outp[((size_t)blockIdx.x * BATCH + mrow_base + row) * ODIM + t * 4] = v;
        }
    }
}

// ---------------- final reduce over the 16 N-groups ----------------
__global__ void reduce_kernel(float* __restrict__ out) {
    int i = blockIdx.x * blockDim.x + threadIdx.x;   // 32768 float4s
    float4 acc = make_float4(0.f, 0.f, 0.f, 0.f);
#pragma unroll
    for (int g = 0; g < NGRP; g++) {
        float4 v = ((const float4*)g_outp)[(size_t)g * (BATCH * 4) + i];
        acc.x += v.x; acc.y += v.y; acc.z += v.z; acc.w += v.w;
    }
    const float s = 1.0f / NUM_TREE;
    ((float4*)out)[i] = make_float4(acc.x * s, acc.y * s, acc.z * s, acc.w * s);
}

// ---------------- launch ----------------
extern "C" void kernel_launch(void* const* d_in, const int* in_sizes, int n_in,
                              void* d_out, int out_size) {
    const float* x     = (const float*)d_in[0];   // [8192, 512]
    const float* W     = (const float*)d_in[1];   // [1984, 512]
    const float* b     = (const float*)d_in[2];   // [1984]
    const float* leafs = (const float*)d_in[3];   // [64, 32, 16]
    float* out = (float*)d_out;                   // [8192, 16]

    leafs_softmax_kernel<<<(NUM_TREE * NL + 255) / 256, 256>>>(leafs);
    prep_x_kernel<<<(BATCH * 256) / 256, 256>>>(x);
    prep_w_kernel<<<dim3(3, 2048), 256>>>(W, b);

    cudaFuncSetAttribute(dndf_mma_kernel,
                         cudaFuncAttributeMaxDynamicSharedMemorySize, SMEM_TOTAL);
    dndf_mma_kernel<<<dim3(NGRP, BATCH / BM), THREADS, SMEM_TOTAL>>>();

    reduce_kernel<<<(BATCH * 4) / 256, 256>>>(out);
}